// round 1
// baseline (speedup 1.0000x reference)
#include <cuda_runtime.h>

#define NCHUNK 8
#define CPC    64          // channels per chunk (512 / 8)
#define CH     512
#define HW     4096        // 64*64
#define NPIX   32768       // 8 * 4096

// Static device scratch (no dynamic allocation allowed).
__device__ __align__(16) float g_p1[NCHUNK][NPIX];
__device__ __align__(16) float g_p2[NCHUNK][NPIX];
__device__ float g_recon[NPIX];
__device__ float g_ref[NPIX];

// ---------------------------------------------------------------------------
// Kernel A: partial channel dot-products.
// grid (32, 8): x = pixel tile of 1024, y = channel chunk of 64. 256 thr/blk,
// each thread owns 4 contiguous pixels (float4) -> fully coalesced 512B/warp.
// ---------------------------------------------------------------------------
__global__ void k_dot(const float* __restrict__ spade, const float* __restrict__ x,
                      const float* __restrict__ w1, const float* __restrict__ w2) {
    __shared__ float sw1[CPC], sw2[CPC];
    const int t = threadIdx.x;
    const int chunk = blockIdx.y;
    if (t < CPC)            sw1[t]       = w1[chunk * CPC + t];
    else if (t < 2 * CPC)   sw2[t - CPC] = w2[chunk * CPC + t - CPC];
    __syncthreads();

    const int P  = blockIdx.x * 1024 + t * 4;     // global pixel base (4 px)
    const int b  = P >> 12;
    const int hw = P & (HW - 1);
    const size_t base = (size_t)b * CH * HW + (size_t)chunk * CPC * HW + hw;
    const float* fp = spade + base;
    const float* xp = x + base;

    float4 a1 = make_float4(0.f, 0.f, 0.f, 0.f);
    float4 a2 = make_float4(0.f, 0.f, 0.f, 0.f);
    #pragma unroll 8
    for (int c = 0; c < CPC; c++) {
        float4 f = *(const float4*)(fp + (size_t)c * HW);
        float4 v = *(const float4*)(xp + (size_t)c * HW);
        const float u = sw1[c];
        const float w = sw2[c];
        a1.x += f.x * u; a1.y += f.y * u; a1.z += f.z * u; a1.w += f.w * u;
        a2.x += v.x * w; a2.y += v.y * w; a2.z += v.z * w; a2.w += v.w * w;
    }
    *(float4*)&g_p1[chunk][P] = a1;
    *(float4*)&g_p2[chunk][P] = a2;
}

// ---------------------------------------------------------------------------
// Kernel B: reduce 8 chunk partials + bias + ReLU -> recon / reference maps.
// ---------------------------------------------------------------------------
__global__ void k_reduce(const float* __restrict__ b1, const float* __restrict__ b2) {
    const int P = blockIdx.x * 256 + threadIdx.x;
    float s1 = b1[0];
    float s2 = b2[0];
    #pragma unroll
    for (int k = 0; k < NCHUNK; k++) {
        s1 += g_p1[k][P];
        s2 += g_p2[k][P];
    }
    g_recon[P] = fmaxf(s1, 0.f);
    g_ref[P]   = fmaxf(s2, 0.f);
}

// ---------------------------------------------------------------------------
// Kernel C: per-patch 2x2 correlation over the padded recon map, argmax with
// first-occurrence tie-break, gather 2x2 patch idx = argmax//4, write output.
// grid 256: block = (b, group of 32 patches). 8 warps, warp-per-patch, 4 each.
// Each lane owns columns (2L, 2L+1); rolling row regs + shfl for q+1 neighbor.
// ---------------------------------------------------------------------------
__global__ void k_match(float* __restrict__ out) {
    __shared__ float R[65][66];   // padded recon tile; row 64 / col 64 = 0
    const int t    = threadIdx.x;
    const int b    = blockIdx.x >> 5;
    const int grp  = blockIdx.x & 31;
    const float* rb = g_recon + b * HW;

    for (int i = t; i < 65 * 66; i += 256) {
        const int row = i / 66;
        const int col = i - row * 66;
        R[row][col] = (row < 64 && col < 64) ? rb[row * 64 + col] : 0.f;
    }
    __syncthreads();

    const int lane = t & 31;
    const int w    = t >> 5;
    const float* refb = g_ref + b * HW;

    for (int k = 0; k < 4; k++) {
        const int l  = grp * 32 + w * 4 + k;
        const int pi = l >> 5;
        const int pj = l & 31;
        // 2x2 "kernel" from the reference map (broadcast loads, all lanes same)
        const float c00 = refb[(2 * pi) * 64 + 2 * pj];
        const float c01 = refb[(2 * pi) * 64 + 2 * pj + 1];
        const float c10 = refb[(2 * pi + 1) * 64 + 2 * pj];
        const float c11 = refb[(2 * pi + 1) * 64 + 2 * pj + 1];

        const int q = lane * 2;
        float2 cur = *(const float2*)&R[0][q];
        float r0 = cur.x, r1 = cur.y;
        float bestv = -1e38f;
        int   besti = 0;

        #pragma unroll 4
        for (int p = 0; p < 64; p++) {
            float2 nxt = *(const float2*)&R[p + 1][q];
            float n0 = nxt.x, n1 = nxt.y;
            float r2 = __shfl_down_sync(0xffffffffu, r0, 1);
            float n2 = __shfl_down_sync(0xffffffffu, n0, 1);
            if (lane == 31) { r2 = 0.f; n2 = 0.f; }   // col 64 is zero pad
            const float y0 = c00 * r0 + c01 * r1 + c10 * n0 + c11 * n1;
            const float y1 = c00 * r1 + c01 * r2 + c10 * n1 + c11 * n2;
            const int idx = (p << 6) + q;
            if (y0 > bestv) { bestv = y0; besti = idx; }
            if (y1 > bestv) { bestv = y1; besti = idx + 1; }
            r0 = n0; r1 = n1;
        }

        // Warp argmax; ties -> smallest flat index (matches jnp.argmax).
        for (int off = 16; off; off >>= 1) {
            const float v2 = __shfl_down_sync(0xffffffffu, bestv, off);
            const int   i2 = __shfl_down_sync(0xffffffffu, besti, off);
            if (v2 > bestv || (v2 == bestv && i2 < besti)) { bestv = v2; besti = i2; }
        }

        if (lane == 0) {
            const int g  = besti >> 2;      // offset // 4
            const int gi = g >> 5;
            const int gj = g & 31;
            float* o = out + b * HW + (2 * pi) * 64 + 2 * pj;
            o[0]  = R[2 * gi][2 * gj];
            o[1]  = R[2 * gi][2 * gj + 1];
            o[64] = R[2 * gi + 1][2 * gj];
            o[65] = R[2 * gi + 1][2 * gj + 1];
        }
    }
}

extern "C" void kernel_launch(void* const* d_in, const int* in_sizes, int n_in,
                              void* d_out, int out_size) {
    const float* spade = (const float*)d_in[0];
    const float* x     = (const float*)d_in[1];
    const float* w1    = (const float*)d_in[2];
    const float* b1    = (const float*)d_in[3];
    const float* w2    = (const float*)d_in[4];
    const float* b2    = (const float*)d_in[5];
    float* out = (float*)d_out;

    k_dot<<<dim3(32, NCHUNK), 256>>>(spade, x, w1, w2);
    k_reduce<<<128, 256>>>(b1, b2);
    k_match<<<256, 256>>>(out);
}

// round 2
// speedup vs baseline: 1.1236x; 1.1236x over previous
#include <cuda_runtime.h>

#define NCHUNK 16
#define CPC    32          // channels per chunk (512 / 16)
#define CH     512
#define HW     4096        // 64*64
#define NPIX   32768       // 8 * 4096

// Static device scratch (no dynamic allocation allowed).
__device__ __align__(16) float g_p1[NCHUNK][NPIX];
__device__ __align__(16) float g_p2[NCHUNK][NPIX];
__device__ float g_recon[NPIX];
__device__ float g_ref[NPIX];

// ---- packed f32x2 helpers (Blackwell FFMA2 path, PTX-only) -----------------
__device__ __forceinline__ unsigned long long pk2(float lo, float hi) {
    unsigned long long r;
    asm("mov.b64 %0, {%1, %2};" : "=l"(r) : "f"(lo), "f"(hi));
    return r;
}
__device__ __forceinline__ void unpk2(unsigned long long v, float& lo, float& hi) {
    asm("mov.b64 {%0, %1}, %2;" : "=f"(lo), "=f"(hi) : "l"(v));
}
__device__ __forceinline__ unsigned long long fma2(unsigned long long a,
                                                   unsigned long long b,
                                                   unsigned long long c) {
    unsigned long long d;
    asm("fma.rn.f32x2 %0, %1, %2, %3;" : "=l"(d) : "l"(a), "l"(b), "l"(c));
    return d;
}
__device__ __forceinline__ unsigned long long mul2(unsigned long long a,
                                                   unsigned long long b) {
    unsigned long long d;
    asm("mul.rn.f32x2 %0, %1, %2;" : "=l"(d) : "l"(a), "l"(b));
    return d;
}

// ---------------------------------------------------------------------------
// Kernel A: partial channel dot-products.
// grid (32, 16): x = pixel tile of 1024, y = channel chunk of 32. 256 thr/blk,
// each thread owns 4 contiguous pixels (float4). 512 blocks -> one full wave,
// ~3.5 blocks/SM resident for latency hiding.
// ---------------------------------------------------------------------------
__global__ void __launch_bounds__(256) k_dot(
        const float* __restrict__ spade, const float* __restrict__ x,
        const float* __restrict__ w1, const float* __restrict__ w2) {
    __shared__ float sw1[CPC], sw2[CPC];
    const int t = threadIdx.x;
    const int chunk = blockIdx.y;
    if (t < CPC)            sw1[t]       = w1[chunk * CPC + t];
    else if (t < 2 * CPC)   sw2[t - CPC] = w2[chunk * CPC + t - CPC];
    __syncthreads();

    const int P  = blockIdx.x * 1024 + t * 4;     // global pixel base (4 px)
    const int b  = P >> 12;
    const int hw = P & (HW - 1);
    const size_t base = (size_t)b * CH * HW + (size_t)chunk * CPC * HW + hw;
    const float* fp = spade + base;
    const float* xp = x + base;

    float4 a1 = make_float4(0.f, 0.f, 0.f, 0.f);
    float4 a2 = make_float4(0.f, 0.f, 0.f, 0.f);
    #pragma unroll 8
    for (int c = 0; c < CPC; c++) {
        float4 f = *(const float4*)(fp + (size_t)c * HW);
        float4 v = *(const float4*)(xp + (size_t)c * HW);
        const float u = sw1[c];
        const float w = sw2[c];
        a1.x += f.x * u; a1.y += f.y * u; a1.z += f.z * u; a1.w += f.w * u;
        a2.x += v.x * w; a2.y += v.y * w; a2.z += v.z * w; a2.w += v.w * w;
    }
    *(float4*)&g_p1[chunk][P] = a1;
    *(float4*)&g_p2[chunk][P] = a2;
}

// ---------------------------------------------------------------------------
// Kernel B: reduce 16 chunk partials + bias + ReLU -> recon / reference maps.
// ---------------------------------------------------------------------------
__global__ void k_reduce(const float* __restrict__ b1, const float* __restrict__ b2) {
    const int P = blockIdx.x * 256 + threadIdx.x;
    float s1 = b1[0];
    float s2 = b2[0];
    #pragma unroll
    for (int k = 0; k < NCHUNK; k++) {
        s1 += g_p1[k][P];
        s2 += g_p2[k][P];
    }
    g_recon[P] = fmaxf(s1, 0.f);
    g_ref[P]   = fmaxf(s2, 0.f);
}

// ---------------------------------------------------------------------------
// Kernel C: per-patch 2x2 correlation over the padded recon map, argmax with
// first-occurrence tie-break, gather 2x2 patch idx = argmax//4, write output.
// grid 512: block = (b, group of 16 patches). 8 warps, 2 patches per warp.
// Each lane owns columns (2L, 2L+1). Inner loop uses packed f32x2 FMA: the
// LDS.64 row pair IS the packed operand; only 1 SHFL per row (neighbor rolls).
// ---------------------------------------------------------------------------
__global__ void __launch_bounds__(256) k_match(float* __restrict__ out) {
    __shared__ float R[65][66];   // padded recon tile; row 64 / col 64 = 0
    const int t    = threadIdx.x;
    const int b    = blockIdx.x >> 6;
    const int grp  = blockIdx.x & 63;
    const float* rb = g_recon + b * HW;

    for (int i = t; i < 65 * 66; i += 256) {
        const int row = i / 66;
        const int col = i - row * 66;
        R[row][col] = (row < 64 && col < 64) ? rb[row * 64 + col] : 0.f;
    }
    __syncthreads();

    const int lane = t & 31;
    const int w    = t >> 5;
    const float* refb = g_ref + b * HW;

    for (int k = 0; k < 2; k++) {
        const int l  = grp * 16 + w * 2 + k;
        const int pi = l >> 5;
        const int pj = l & 31;
        // 2x2 "kernel" from the reference map (broadcast loads, all lanes same)
        const float c00 = refb[(2 * pi) * 64 + 2 * pj];
        const float c01 = refb[(2 * pi) * 64 + 2 * pj + 1];
        const float c10 = refb[(2 * pi + 1) * 64 + 2 * pj];
        const float c11 = refb[(2 * pi + 1) * 64 + 2 * pj + 1];
        const unsigned long long cc00 = pk2(c00, c00);
        const unsigned long long cc01 = pk2(c01, c01);
        const unsigned long long cc10 = pk2(c10, c10);
        const unsigned long long cc11 = pk2(c11, c11);

        const int q = lane * 2;
        // row 0 pair + right neighbor
        float2 a = *(const float2*)&R[0][q];
        float a2 = __shfl_down_sync(0xffffffffu, a.x, 1);
        if (lane == 31) a2 = 0.f;                 // col 64 zero pad
        unsigned long long v01 = pk2(a.x, a.y);
        unsigned long long v12 = pk2(a.y, a2);

        float bestv = -1.f;                        // all y >= 0 (ReLU inputs)
        int   besti = 0;

        #pragma unroll 4
        for (int p = 0; p < 64; p++) {
            float2 nb = *(const float2*)&R[p + 1][q];
            float n2 = __shfl_down_sync(0xffffffffu, nb.x, 1);
            if (lane == 31) n2 = 0.f;
            const unsigned long long w01 = pk2(nb.x, nb.y);
            const unsigned long long w12 = pk2(nb.y, n2);
            // y_pair = c00*v01 + c01*v12 + c10*w01 + c11*w12  (packed, 2 lanes)
            unsigned long long yp =
                fma2(cc11, w12, fma2(cc10, w01, fma2(cc01, v12, mul2(cc00, v01))));
            float y0, y1;
            unpk2(yp, y0, y1);
            const int idx = (p << 6) + q;
            if (y0 > bestv) { bestv = y0; besti = idx; }
            if (y1 > bestv) { bestv = y1; besti = idx + 1; }
            v01 = w01; v12 = w12;
        }

        // Warp argmax; ties -> smallest flat index (matches jnp.argmax).
        for (int off = 16; off; off >>= 1) {
            const float v2 = __shfl_down_sync(0xffffffffu, bestv, off);
            const int   i2 = __shfl_down_sync(0xffffffffu, besti, off);
            if (v2 > bestv || (v2 == bestv && i2 < besti)) { bestv = v2; besti = i2; }
        }

        if (lane == 0) {
            const int g  = besti >> 2;      // offset // 4
            const int gi = g >> 5;
            const int gj = g & 31;
            float* o = out + b * HW + (2 * pi) * 64 + 2 * pj;
            o[0]  = R[2 * gi][2 * gj];
            o[1]  = R[2 * gi][2 * gj + 1];
            o[64] = R[2 * gi + 1][2 * gj];
            o[65] = R[2 * gi + 1][2 * gj + 1];
        }
    }
}

extern "C" void kernel_launch(void* const* d_in, const int* in_sizes, int n_in,
                              void* d_out, int out_size) {
    const float* spade = (const float*)d_in[0];
    const float* x     = (const float*)d_in[1];
    const float* w1    = (const float*)d_in[2];
    const float* b1    = (const float*)d_in[3];
    const float* w2    = (const float*)d_in[4];
    const float* b2    = (const float*)d_in[5];
    float* out = (float*)d_out;

    k_dot<<<dim3(32, NCHUNK), 256>>>(spade, x, w1, w2);
    k_reduce<<<128, 256>>>(b1, b2);
    k_match<<<512, 256>>>(out);
}